// round 17
// baseline (speedup 1.0000x reference)
#include <cuda_runtime.h>
#include <cuda_fp16.h>
#include <cstdint>

#define EPSV 1e-5f
#define NB   16
#define CC   128
#define C2   64
#define CR   8
#define HWn  16384
#define TPX2 256
#define KTOT 256

typedef unsigned long long u64;

__device__ __forceinline__ void cp16(void* s, const void* g){
    unsigned sa = (unsigned)__cvta_generic_to_shared(s);
    asm volatile("cp.async.cg.shared.global [%0], [%1], 16;" :: "r"(sa), "l"(g));
}
#define CP_COMMIT() asm volatile("cp.async.commit_group;")
#define CP_WAIT1()  asm volatile("cp.async.wait_group 1;")
#define CP_WAIT0()  asm volatile("cp.async.wait_group 0;")

// ---------------- device scratch (no allocations allowed) ----------------
__device__ __align__(16) float  g_pooled[NB*KTOT];
__device__ __align__(16) float  g_wch[NB*CC];
__device__ __align__(16) __half g_h[(size_t)NB*KTOT*HWn];   // fp16 copy of [f_vi;f_ir]
__device__ __align__(16) __half g_Wh[NB*32768];             // fp16 W, m16n8k16 A-fragment order
__device__ __align__(16) float  g_beta[CC];
__device__ __align__(16) float  g_chansum[NB*CC];
__device__             int    g_chanmax[NB*CC];             // float bits, g >= 0
__device__ __align__(16) float  g_spsum[NB*HWn];
__device__ __align__(16) float  g_spmax[NB*HWn];
__device__ __align__(16) float  g_ca[NB*CC];
__device__ __align__(16) float  g_sa[NB*HWn];

__device__ __forceinline__ float sigmoidf_(float x){ return 1.0f/(1.0f + expf(-x)); }

// ------- K1: channel-wise spatial mean of [f_vi; f_ir] + fp16 copy -------
__global__ void k_pool(const float* __restrict__ fvi, const float* __restrict__ fir){
    int ch = blockIdx.x; int n = blockIdx.y; int tid = threadIdx.x;
    const float* src = (ch < CC) ? (fvi + ((size_t)(n*CC + ch))*HWn)
                                 : (fir + ((size_t)(n*CC + ch - CC))*HWn);
    const float4* s4 = (const float4*)src;
    __half* hdst = g_h + ((size_t)(n*KTOT + ch))*HWn;
    float s = 0.f;
    for (int i = tid; i < HWn/4; i += 256){
        float4 v = s4[i];
        s += (v.x+v.y)+(v.z+v.w);
        __half2 h0 = __floats2half2_rn(v.x, v.y);
        __half2 h1 = __floats2half2_rn(v.z, v.w);
        uint2 pk; pk.x = *(unsigned*)&h0; pk.y = *(unsigned*)&h1;
        *(uint2*)(hdst + i*4) = pk;
    }
    for (int d = 16; d; d >>= 1) s += __shfl_xor_sync(0xffffffffu, s, d);
    __shared__ float ws[8];
    if ((tid & 31) == 0) ws[tid >> 5] = s;
    __syncthreads();
    if (tid == 0){
        float t = 0.f;
        #pragma unroll
        for (int i = 0; i < 8; ++i) t += ws[i];
        g_pooled[n*KTOT + ch] = t * (1.0f/HWn);
    }
}

// ---------------- K2a: channel-attention MLP -> wch[n][c] ----------------
__global__ void k_wch(const float* __restrict__ ca1_w, const float* __restrict__ ca1_b,
                      const float* __restrict__ bna_g, const float* __restrict__ bna_b,
                      const float* __restrict__ bna_m, const float* __restrict__ bna_v,
                      const float* __restrict__ ca2_w, const float* __restrict__ ca2_b,
                      const float* __restrict__ bnb_g, const float* __restrict__ bnb_b,
                      const float* __restrict__ bnb_m, const float* __restrict__ bnb_v){
    int n = blockIdx.x; int tid = threadIdx.x; int lane = tid & 31; int w = tid >> 5;
    __shared__ float pool_s[KTOT];
    __shared__ float h_s[C2];
    for (int i = tid; i < KTOT; i += 256) pool_s[i] = g_pooled[n*KTOT + i];
    __syncthreads();
    for (int jj = 0; jj < 8; ++jj){
        int j = w*8 + jj;
        float s = 0.f;
        for (int k = lane; k < KTOT; k += 32) s += pool_s[k]*__ldg(&ca1_w[j*KTOT + k]);
        for (int d = 16; d; d >>= 1) s += __shfl_xor_sync(0xffffffffu, s, d);
        if (lane == 0){
            float sa = bna_g[j]*rsqrtf(bna_v[j] + EPSV);
            h_s[j] = fmaxf(0.f, (s + ca1_b[j] - bna_m[j])*sa + bna_b[j]);
        }
    }
    __syncthreads();
    if (tid < CC){
        int o = tid; float s = 0.f;
        #pragma unroll 8
        for (int j = 0; j < C2; ++j) s += h_s[j]*__ldg(&ca2_w[o*C2 + j]);
        float sb = bnb_g[o]*rsqrtf(bnb_v[o] + EPSV);
        g_wch[n*CC + o] = sigmoidf_((s + ca2_b[o] - bnb_m[o])*sb + bnb_b[o]);
    }
}

// ---- K2b: effective weights -> fp16, m16n8k16 A-fragment order ----
// per n: [chunk(16)][mt(8)][lane(32)][reg(4)][half(2)]
__global__ void k_mkw(const float* __restrict__ cw, const float* __restrict__ c1b,
                      const float* __restrict__ bnc_g, const float* __restrict__ bnc_b,
                      const float* __restrict__ bnc_m, const float* __restrict__ bnc_v){
    int idx = blockIdx.x*256 + threadIdx.x;           // 524288 threads exactly
    int o = idx & 127; int k = (idx >> 7) & 255; int n = idx >> 15;
    float sc = bnc_g[o]*rsqrtf(bnc_v[o] + EPSV);
    int c = k & 127;
    float w1v = __ldg(&cw[o*KTOT + c]);
    float w2v = __ldg(&cw[o*KTOT + CC + c]);
    float wc  = __ldg(&g_wch[n*CC + c]);
    float val = (k < CC) ? sc*(w1v + wc*w2v) : sc*(w2v + wc*w1v);
    int chunk = k >> 4, e = k & 15;
    int mt = o >> 4, r = o & 15, rlo = r & 7, rhi = r >> 3;
    int lane = rlo*4 + ((e & 7) >> 1);
    int reg  = (e >> 3)*2 + rhi;
    size_t off = ((((size_t)n*16 + chunk)*8 + mt)*32 + lane)*8 + reg*2 + (e & 1);
    g_Wh[off] = __float2half_rn(val);
    if (idx < CC){
        float s2 = bnc_g[idx]*rsqrtf(bnc_v[idx] + EPSV);
        g_beta[idx] = bnc_b[idx] + s2*(c1b[idx] - bnc_m[idx]);
    }
    if (idx < NB*CC){ g_chansum[idx] = 0.f; g_chanmax[idx] = 0; }
}

// -------- K3: fp16 mma.sync GEMM, D[128o x 256px] per CTA, fused reductions --------
// warp tile 64o x 64px; 3-stage cp.async pipeline; B via ldmatrix.x4.trans
__global__ __launch_bounds__(256,1) void k_main(void){
    __shared__ __align__(128) unsigned char sbm[3*12288];  // buf: [W 4KB][B 8KB]
    __shared__ float cs[CC]; __shared__ int cmi[CC];
    __shared__ float psp[2][TPX2], pmp[2][TPX2];

    int tid = threadIdx.x; int w = tid >> 5, lane = tid & 31;
    int klo = lane & 3, pxl = lane >> 2;
    int ob = (w & 1)*64, pb = (w >> 1)*64;
    int n = blockIdx.y; int p0 = blockIdx.x * TPX2;

    if (tid < CC){ cs[tid] = 0.f; cmi[tid] = 0; }

    float acc[4][8][4];
    #pragma unroll
    for (int i = 0; i < 4; ++i)
        #pragma unroll
        for (int j = 0; j < 8; ++j)
            #pragma unroll
            for (int e = 0; e < 4; ++e) acc[i][j][e] = 0.f;

    const unsigned char* wg = (const unsigned char*)(g_Wh + (size_t)n*32768);

    auto load_chunk = [&](int c, int buf){
        unsigned char* base = sbm + buf*12288;
        cp16(base + tid*16, wg + c*4096 + tid*16);
        // B chunk: 16k x 256px fp16 = 8KB = 512 slots of 16B
        #pragma unroll
        for (int i = 0; i < 2; ++i){
            int slot = tid + 256*i;
            int k = slot >> 5; int px0 = (slot & 31) << 3;
            unsigned off = (unsigned)(k*512 + px0*2) ^ (unsigned)((k & 7) << 4);
            cp16(base + 4096 + off,
                 g_h + ((size_t)(n*KTOT + c*16 + k))*HWn + p0 + px0);
        }
    };

    load_chunk(0, 0); CP_COMMIT();
    load_chunk(1, 1); CP_COMMIT();
    int bmi = lane >> 3, brow = lane & 7;
    int bkk = brow + (bmi & 1)*8;
    #pragma unroll
    for (int c = 0; c < 16; ++c){
        int buf = c % 3;
        if (c < 15) CP_WAIT1(); else CP_WAIT0();   // group c complete
        __syncthreads();                           // data visible + compute c-1 retired
        if (c < 14){ load_chunk(c + 2, (c + 2) % 3); CP_COMMIT(); }
        const unsigned char* wb = sbm + buf*12288;
        const unsigned char* bb = wb + 4096;
        uint32_t a[4][4];
        #pragma unroll
        for (int mt = 0; mt < 4; ++mt){
            uint4 av = *(const uint4*)(wb + (((w & 1)*4 + mt)*32 + lane)*16);
            a[mt][0] = av.x; a[mt][1] = av.y; a[mt][2] = av.z; a[mt][3] = av.w;
        }
        uint32_t bfr[4][4];
        #pragma unroll
        for (int ntp = 0; ntp < 4; ++ntp){
            int pxb = pb + ntp*16 + (bmi >> 1)*8;
            unsigned off = (unsigned)(bkk*512 + pxb*2) ^ (unsigned)((bkk & 7) << 4);
            unsigned addr = (unsigned)__cvta_generic_to_shared(bb + off);
            asm volatile("ldmatrix.sync.aligned.m8n8.x4.trans.shared.b16 {%0,%1,%2,%3}, [%4];"
                : "=r"(bfr[ntp][0]), "=r"(bfr[ntp][1]), "=r"(bfr[ntp][2]), "=r"(bfr[ntp][3])
                : "r"(addr));
        }
        #pragma unroll
        for (int mt = 0; mt < 4; ++mt)
            #pragma unroll
            for (int nt = 0; nt < 8; ++nt){
                uint32_t b0 = bfr[nt >> 1][(nt & 1)*2];
                uint32_t b1 = bfr[nt >> 1][(nt & 1)*2 + 1];
                asm("mma.sync.aligned.m16n8k16.row.col.f32.f16.f16.f32 "
                    "{%0,%1,%2,%3},{%4,%5,%6,%7},{%8,%9},{%0,%1,%2,%3};"
                    : "+f"(acc[mt][nt][0]), "+f"(acc[mt][nt][1]),
                      "+f"(acc[mt][nt][2]), "+f"(acc[mt][nt][3])
                    : "r"(a[mt][0]), "r"(a[mt][1]), "r"(a[mt][2]), "r"(a[mt][3]),
                      "r"(b0), "r"(b1));
            }
    }
    __syncthreads();   // all compute done before epilogue shared-atomics ordering

    // ---- epilogue: relu(acc+beta) in-place ----
    #pragma unroll
    for (int mt = 0; mt < 4; ++mt){
        float b0 = __ldg(&g_beta[ob + mt*16 + pxl]);
        float b1 = __ldg(&g_beta[ob + mt*16 + pxl + 8]);
        #pragma unroll
        for (int nt = 0; nt < 8; ++nt){
            acc[mt][nt][0] = fmaxf(acc[mt][nt][0] + b0, 0.f);
            acc[mt][nt][1] = fmaxf(acc[mt][nt][1] + b0, 0.f);
            acc[mt][nt][2] = fmaxf(acc[mt][nt][2] + b1, 0.f);
            acc[mt][nt][3] = fmaxf(acc[mt][nt][3] + b1, 0.f);
        }
    }
    // channel partials: rows r=pxl (+8) per mt; reduce over cols (lanes xor 1,2)
    {
        float rs[8], rm[8];
        #pragma unroll
        for (int mt = 0; mt < 4; ++mt){
            float s0 = 0.f, s1 = 0.f, m0 = 0.f, m1 = 0.f;
            #pragma unroll
            for (int nt = 0; nt < 8; ++nt){
                s0 += acc[mt][nt][0] + acc[mt][nt][1];
                s1 += acc[mt][nt][2] + acc[mt][nt][3];
                m0 = fmaxf(m0, fmaxf(acc[mt][nt][0], acc[mt][nt][1]));
                m1 = fmaxf(m1, fmaxf(acc[mt][nt][2], acc[mt][nt][3]));
            }
            rs[mt*2] = s0; rs[mt*2+1] = s1; rm[mt*2] = m0; rm[mt*2+1] = m1;
        }
        #pragma unroll
        for (int i = 0; i < 8; ++i){
            rs[i] += __shfl_xor_sync(0xffffffffu, rs[i], 1);
            rs[i] += __shfl_xor_sync(0xffffffffu, rs[i], 2);
            rm[i] = fmaxf(rm[i], __shfl_xor_sync(0xffffffffu, rm[i], 1));
            rm[i] = fmaxf(rm[i], __shfl_xor_sync(0xffffffffu, rm[i], 2));
        }
        if (klo == 0){
            #pragma unroll
            for (int mt = 0; mt < 4; ++mt)
                #pragma unroll
                for (int h = 0; h < 2; ++h){
                    int o = ob + mt*16 + h*8 + pxl;
                    atomicAdd(&cs[o], rs[mt*2 + h]);
                    atomicMax(&cmi[o], __float_as_int(rm[mt*2 + h]));
                }
        }
    }
    // px partials: cols 2*klo+j per nt; reduce over rows (lanes xor 4,8,16)
    {
        float qs[16], qm[16];
        #pragma unroll
        for (int nt = 0; nt < 8; ++nt)
            #pragma unroll
            for (int j = 0; j < 2; ++j){
                float s = 0.f, m = 0.f;
                #pragma unroll
                for (int mt = 0; mt < 4; ++mt){
                    s += acc[mt][nt][j] + acc[mt][nt][j+2];
                    m = fmaxf(m, fmaxf(acc[mt][nt][j], acc[mt][nt][j+2]));
                }
                qs[nt*2 + j] = s; qm[nt*2 + j] = m;
            }
        #pragma unroll
        for (int i = 0; i < 16; ++i){
            qs[i] += __shfl_xor_sync(0xffffffffu, qs[i], 4);
            qs[i] += __shfl_xor_sync(0xffffffffu, qs[i], 8);
            qs[i] += __shfl_xor_sync(0xffffffffu, qs[i], 16);
            qm[i] = fmaxf(qm[i], __shfl_xor_sync(0xffffffffu, qm[i], 4));
            qm[i] = fmaxf(qm[i], __shfl_xor_sync(0xffffffffu, qm[i], 8));
            qm[i] = fmaxf(qm[i], __shfl_xor_sync(0xffffffffu, qm[i], 16));
        }
        if (lane < 4){
            #pragma unroll
            for (int nt = 0; nt < 8; ++nt)
                #pragma unroll
                for (int j = 0; j < 2; ++j){
                    int col = pb + nt*8 + 2*lane + j;
                    psp[w & 1][col] = qs[nt*2 + j];
                    pmp[w & 1][col] = qm[nt*2 + j];
                }
        }
    }
    __syncthreads();
    {
        g_spsum[n*HWn + p0 + tid] = psp[0][tid] + psp[1][tid];
        g_spmax[n*HWn + p0 + tid] = fmaxf(pmp[0][tid], pmp[1][tid]);
        if (tid < CC){
            atomicAdd(&g_chansum[n*CC + tid], cs[tid]);
            atomicMax(&g_chanmax[n*CC + tid], cmi[tid]);
        }
    }
}

// ---------------- K4a: CBAM channel attention -> ca[n][o] ----------------
__global__ void k_ca(const float* __restrict__ w1, const float* __restrict__ w2){
    __shared__ float avg_s[NB*CC], mx_s[NB*CC], hs[NB*CR];
    int tid = threadIdx.x;
    for (int i = tid; i < NB*CC; i += 256){
        avg_s[i] = g_chansum[i]*(1.0f/HWn);
        mx_s[i]  = __int_as_float(g_chanmax[i]);
    }
    __syncthreads();
    if (tid < NB*CR){
        int n = tid >> 3, r = tid & 7;
        float da = 0.f, dm = 0.f;
        for (int c = 0; c < CC; ++c){
            float wv = __ldg(&w1[r*CC + c]);
            da += avg_s[n*CC + c]*wv;
            dm += mx_s[n*CC + c]*wv;
        }
        hs[tid] = fmaxf(da, 0.f) + fmaxf(dm, 0.f);
    }
    __syncthreads();
    for (int i = tid; i < NB*CC; i += 256){
        int n = i >> 7, o = i & 127;
        float y = 0.f;
        #pragma unroll
        for (int r = 0; r < CR; ++r) y += hs[n*CR + r]*__ldg(&w2[o*CR + r]);
        g_ca[i] = sigmoidf_(y);
    }
}

// ---------------- K4b: 7x7 spatial conv + sigmoid -> sa[n][p] ----------------
__global__ void k_sa(const float* __restrict__ saw){
    __shared__ float in_s[2][22][22];
    __shared__ float w_s[98];
    int n = blockIdx.y; int t = blockIdx.x;
    int ty0 = (t >> 3)*16, tx0 = (t & 7)*16;
    int tx = threadIdx.x, ty = threadIdx.y;
    int lt = ty*16 + tx;
    if (lt < 98) w_s[lt] = saw[lt];
    for (int i = lt; i < 2*22*22; i += 256){
        int ch = i / 484; int rr = i % 484; int yy = rr / 22, xx = rr % 22;
        int gy = ty0 - 3 + yy, gx = tx0 - 3 + xx;
        float v = 0.f;
        if (gy >= 0 && gy < 128 && gx >= 0 && gx < 128){
            int off = n*HWn + gy*128 + gx;
            v = (ch == 0) ? g_spsum[off]*(1.0f/CC) : g_spmax[off];
        }
        in_s[ch][yy][xx] = v;
    }
    __syncthreads();
    float acc = 0.f;
    #pragma unroll
    for (int ch = 0; ch < 2; ++ch)
        #pragma unroll
        for (int ky = 0; ky < 7; ++ky)
            #pragma unroll
            for (int kx = 0; kx < 7; ++kx)
                acc += in_s[ch][ty + ky][tx + kx]*w_s[ch*49 + ky*7 + kx];
    g_sa[n*HWn + (ty0 + ty)*128 + tx0 + tx] = sigmoidf_(acc);
}

// ---------------- K5: final blend ----------------
__global__ void k_out(const float* __restrict__ fvi, const float* __restrict__ fir,
                      float* __restrict__ out){
    int c = blockIdx.x, n = blockIdx.y, tid = threadIdx.x;
    size_t base = ((size_t)n*CC + c)*HWn;
    float wc  = g_wch[n*CC + c];
    float cav = g_ca[n*CC + c];
    const float4* v4 = (const float4*)(fvi + base);
    const float4* i4 = (const float4*)(fir + base);
    const float4* s4 = (const float4*)(g_sa + (size_t)n*HWn);
    float4* o4 = (float4*)(out + base);
    for (int i = tid; i < HWn/4; i += 256){
        float4 a = v4[i], b = i4[i], s = s4[i];
        float4 r;
        {
            float wgt = sigmoidf_(s.x*cav);
            float fv2 = fmaf(b.x, wc, a.x), fi2 = fmaf(a.x, wc, b.x);
            r.x = fi2 + wgt*(fv2 - fi2);
        }
        {
            float wgt = sigmoidf_(s.y*cav);
            float fv2 = fmaf(b.y, wc, a.y), fi2 = fmaf(a.y, wc, b.y);
            r.y = fi2 + wgt*(fv2 - fi2);
        }
        {
            float wgt = sigmoidf_(s.z*cav);
            float fv2 = fmaf(b.z, wc, a.z), fi2 = fmaf(a.z, wc, b.z);
            r.z = fi2 + wgt*(fv2 - fi2);
        }
        {
            float wgt = sigmoidf_(s.w*cav);
            float fv2 = fmaf(b.w, wc, a.w), fi2 = fmaf(a.w, wc, b.w);
            r.w = fi2 + wgt*(fv2 - fi2);
        }
        o4[i] = r;
    }
}

// ---------------- launcher ----------------
extern "C" void kernel_launch(void* const* d_in, const int* in_sizes, int n_in,
                              void* d_out, int out_size){
    const float* fvi    = (const float*)d_in[0];
    const float* fir    = (const float*)d_in[1];
    const float* ca1_w  = (const float*)d_in[2];
    const float* ca1_b  = (const float*)d_in[3];
    const float* bna_g  = (const float*)d_in[4];
    const float* bna_b  = (const float*)d_in[5];
    const float* bna_m  = (const float*)d_in[6];
    const float* bna_v  = (const float*)d_in[7];
    const float* ca2_w  = (const float*)d_in[8];
    const float* ca2_b  = (const float*)d_in[9];
    const float* bnb_g  = (const float*)d_in[10];
    const float* bnb_b  = (const float*)d_in[11];
    const float* bnb_m  = (const float*)d_in[12];
    const float* bnb_v  = (const float*)d_in[13];
    const float* cw     = (const float*)d_in[14];
    const float* c1b    = (const float*)d_in[15];
    const float* bnc_g  = (const float*)d_in[16];
    const float* bnc_b  = (const float*)d_in[17];
    const float* bnc_m  = (const float*)d_in[18];
    const float* bnc_v  = (const float*)d_in[19];
    const float* w1     = (const float*)d_in[20];
    const float* w2     = (const float*)d_in[21];
    const float* saw    = (const float*)d_in[22];

    k_pool<<<dim3(256, NB), 256>>>(fvi, fir);
    k_wch <<<NB, 256>>>(ca1_w, ca1_b, bna_g, bna_b, bna_m, bna_v,
                        ca2_w, ca2_b, bnb_g, bnb_b, bnb_m, bnb_v);
    k_mkw <<<2048, 256>>>(cw, c1b, bnc_g, bnc_b, bnc_m, bnc_v);
    k_main<<<dim3(HWn/TPX2, NB), 256>>>();
    k_ca  <<<1, 256>>>(w1, w2);
    k_sa  <<<dim3(64, NB), dim3(16, 16)>>>(saw);
    k_out <<<dim3(CC, NB), 256>>>(fvi, fir, (float*)d_out);
}